// round 16
// baseline (speedup 1.0000x reference)
#include <cuda_runtime.h>
#include <cuda_bf16.h>
#include <math.h>
#include <stdint.h>

#define B_   2
#define N_   1024
#define D_   768
#define H_   16
#define HD_  48
#define HID_ 1536
#define M_   (B_*N_)      // 2048
#define EPS_ 1e-5f

// ---------------- fp32 scratch ----------------
__device__ float g_q   [M_*D_];
__device__ float g_k   [M_*D_];
__device__ float g_v   [M_*D_];
__device__ float g_gt  [M_*D_];
__device__ float g_anew[M_*D_];

// ---------------- bf16 scratch (16B aligned for cp.async) ----------------
#define DD_ 589824                            // 768*768
#define OFF_SWISH (11*DD_)
#define OFF_A2B   (OFF_SWISH + D_*2*HID_)
#define OFF_B2A   (OFF_A2B + D_*HID_)
#define WBF_TOTAL (OFF_B2A + HID_*D_)
__device__ __align__(16) __nv_bfloat16 g_wbf  [WBF_TOTAL];
__device__ __align__(16) __nv_bfloat16 g_sbf  [M_*D_];
__device__ __align__(16) __nv_bfloat16 g_sn1bf[M_*D_];
__device__ __align__(16) __nv_bfloat16 g_sn2bf[M_*D_];
__device__ __align__(16) __nv_bfloat16 g_c1bf [M_*D_];
__device__ __align__(16) __nv_bfloat16 g_c2bf [M_*D_];
__device__ __align__(16) __nv_bfloat16 g_c1bbf[M_*D_];
__device__ __align__(16) __nv_bfloat16 g_c2bbf[M_*D_];
__device__ __align__(16) __nv_bfloat16 g_sgbf [M_*D_];
__device__ __align__(16) __nv_bfloat16 g_sg2bf[M_*D_];
__device__ __align__(16) __nv_bfloat16 g_bmbf [M_*D_];
__device__ __align__(16) __nv_bfloat16 g_ogbf [M_*D_];
__device__ __align__(16) __nv_bfloat16 g_swbf [M_*2*HID_];
__device__ __align__(16) __nv_bfloat16 g_abbf [M_*HID_];
__device__ __align__(16) __nv_bfloat16 g_hidbf[M_*HID_];

// =================================================================================
// helpers
// =================================================================================
__device__ __forceinline__ uint32_t smem_u32(const void* p) {
    uint32_t a;
    asm("{ .reg .u64 t; cvta.to.shared.u64 t, %1; cvt.u32.u64 %0, t; }" : "=r"(a) : "l"(p));
    return a;
}
__device__ __forceinline__ uint32_t f2tf32(float f) {
    uint32_t u;
    asm("cvt.rna.tf32.f32 %0, %1;" : "=r"(u) : "f"(f));
    return u;
}
__device__ __forceinline__ void mma_m16n8k8(float* c, const uint32_t* a, const uint32_t* b) {
    asm volatile(
        "mma.sync.aligned.m16n8k8.row.col.f32.tf32.tf32.f32 "
        "{%0,%1,%2,%3}, {%4,%5,%6,%7}, {%8,%9}, {%0,%1,%2,%3};"
        : "+f"(c[0]), "+f"(c[1]), "+f"(c[2]), "+f"(c[3])
        : "r"(a[0]), "r"(a[1]), "r"(a[2]), "r"(a[3]), "r"(b[0]), "r"(b[1]));
}
__device__ __forceinline__ void mma_bf16(float* c, const uint32_t* a, const uint32_t* b) {
    asm volatile(
        "mma.sync.aligned.m16n8k16.row.col.f32.bf16.bf16.f32 "
        "{%0,%1,%2,%3}, {%4,%5,%6,%7}, {%8,%9}, {%0,%1,%2,%3};"
        : "+f"(c[0]), "+f"(c[1]), "+f"(c[2]), "+f"(c[3])
        : "r"(a[0]), "r"(a[1]), "r"(a[2]), "r"(a[3]), "r"(b[0]), "r"(b[1]));
}
__device__ __forceinline__ void ldsm_x4(uint32_t* r, uint32_t addr) {
    asm volatile("ldmatrix.sync.aligned.m8n8.x4.shared.b16 {%0,%1,%2,%3}, [%4];"
        : "=r"(r[0]), "=r"(r[1]), "=r"(r[2]), "=r"(r[3]) : "r"(addr));
}
__device__ __forceinline__ void ldsm_x4_t(uint32_t* r, uint32_t addr) {
    asm volatile("ldmatrix.sync.aligned.m8n8.x4.trans.shared.b16 {%0,%1,%2,%3}, [%4];"
        : "=r"(r[0]), "=r"(r[1]), "=r"(r[2]), "=r"(r[3]) : "r"(addr));
}
__device__ __forceinline__ uint2 f4_to_bf16x4(float4 v) {
    __nv_bfloat162 lo = __float22bfloat162_rn(make_float2(v.x, v.y));
    __nv_bfloat162 hi = __float22bfloat162_rn(make_float2(v.z, v.w));
    uint2 r;
    r.x = *(uint32_t*)&lo;
    r.y = *(uint32_t*)&hi;
    return r;
}
__device__ __forceinline__ uint32_t f2_to_bf16x2(float a, float b) {
    __nv_bfloat162 p = __float22bfloat162_rn(make_float2(a, b));
    return *(uint32_t*)&p;
}
__device__ __forceinline__ float2 bf2_to_f2(const __nv_bfloat16* p) {
    return __bfloat1622float2(*(const __nv_bfloat162*)p);
}
__device__ __forceinline__ void cp16(uint32_t saddr, const void* gaddr) {
    asm volatile("cp.async.cg.shared.global [%0], [%1], 16;" :: "r"(saddr), "l"(gaddr));
}

// ---------------- block reduction ----------------
__device__ __forceinline__ float block_reduce_sum(float v) {
    __shared__ float sh[8];
    __shared__ float res;
    __syncthreads();
    #pragma unroll
    for (int o = 16; o > 0; o >>= 1) v += __shfl_down_sync(0xffffffffu, v, o);
    int lane = threadIdx.x & 31, w = threadIdx.x >> 5;
    if (lane == 0) sh[w] = v;
    __syncthreads();
    if (w == 0) {
        v = (lane < 8) ? sh[lane] : 0.f;
        #pragma unroll
        for (int o = 4; o > 0; o >>= 1) v += __shfl_down_sync(0xffffffffu, v, o);
        if (lane == 0) res = v;
    }
    __syncthreads();
    return res;
}

// =================================================================================
// combined kernel: y<15 -> fp32->bf16 conversion segments (grid-stride);
//                  y==15 -> bf16 ln(s)*w1; y==16 -> bf16 ln(s)*w2
// =================================================================================
struct CSeg { const float* src; __nv_bfloat16* dst; int n4; };
struct CPack { CSeg s[15]; };
__global__ __launch_bounds__(256) void conv_ln_kernel(CPack pk,
                                                      const float* __restrict__ x,
                                                      const float* __restrict__ w1,
                                                      const float* __restrict__ w2,
                                                      __nv_bfloat16* __restrict__ o1,
                                                      __nv_bfloat16* __restrict__ o2) {
    if (blockIdx.y < 15) {
        const CSeg sg = pk.s[blockIdx.y];
        for (int i = blockIdx.x * 256 + threadIdx.x; i < sg.n4; i += gridDim.x * 256) {
            ((uint2*)sg.dst)[i] = f4_to_bf16x4(((const float4*)sg.src)[i]);
        }
    } else {
        const int row = blockIdx.x;
        const float* xr = x + (size_t)row * D_;
        float lv[3];
        float s = 0.f;
        #pragma unroll
        for (int i = 0; i < 3; i++) { lv[i] = xr[threadIdx.x + i*256]; s += lv[i]; }
        float mean = block_reduce_sum(s) * (1.f / D_);
        float vs = 0.f;
        #pragma unroll
        for (int i = 0; i < 3; i++) { float d = lv[i] - mean; vs += d * d; }
        float var = block_reduce_sum(vs) * (1.f / D_);
        float rstd = rsqrtf(var + EPS_);
        const float* w = (blockIdx.y == 15) ? w1 : w2;
        __nv_bfloat16* orow = ((blockIdx.y == 15) ? o1 : o2) + (size_t)row * D_;
        #pragma unroll
        for (int i = 0; i < 3; i++) {
            int c = threadIdx.x + i*256;
            orow[c] = __float2bfloat16((lv[i] - mean) * rstd * w[c]);
        }
    }
}

// =================================================================================
// multi-slice bf16 GEMM: 128x128x64 iteration, cp.async STAGES-deep pipeline.
//   MODE=0: fp32 C = acc+bias (act=1 -> sigmoid)
//   MODE=2: fp32 C = R + G*acc   (R fp32, G bf16)
//   MODE=3: bf16 C = acc+bias (act=1 -> sigmoid)
// STAGES=3 for packed launches (2 CTAs/SM), STAGES=6 for solo launches (1 CTA/SM,
// deep prefetch hides DRAM/L2 latency on the serial K chain).
// =================================================================================
struct GSlice {
    const __nv_bfloat16* A; const __nv_bfloat16* W; const float* bias;
    const float* R; const __nv_bfloat16* G; float* C;
    int K; int Wstride; int Cstride; int act;
};
struct GPack { GSlice s[6]; };

#define A_ROWB 144
#define B_ROWB 272
#define A_STG  (128*A_ROWB)         // 18432 B
#define STG_T  (A_STG + 64*B_ROWB)  // 35840 B per stage

template<int MODE, int STAGES>
__global__ __launch_bounds__(256, 2) void mma_gemm_kernel(GPack pk, int Ndim)
{
    extern __shared__ char sm[];
    const uint32_t sb = smem_u32(sm);

    const GSlice sl = pk.s[blockIdx.z];
    const char* A8 = (const char*)sl.A;
    const char* W8 = (const char*)sl.W;
    const int Kdim = sl.K, Wstr = sl.Wstride, Cstr = sl.Cstride, act = sl.act;

    const int tid  = threadIdx.x;
    const int lane = tid & 31, wid = tid >> 5;
    const int wm0  = (wid >> 2) * 64;
    const int wn0  = (wid & 3) * 32;
    const int tq   = lane >> 2, tr = lane & 3;
    const int bm   = blockIdx.y * 128, bn = blockIdx.x * 128;

    const int ar0 = tid >> 3,  ac16 = (tid & 7) * 16;
    const int br0 = tid >> 4,  bc16 = (tid & 15) * 16;

    const int lm  = lane >> 3;
    const int li  = lane & 7;
    const int a_r = (lm & 1) * 8 + li, a_k = (lm >> 1) * 8;
    const int b_k = (lm & 1) * 8 + li, b_n = (lm >> 1) * 8;

    float acc[4][4][4];
    #pragma unroll
    for (int i = 0; i < 4; i++)
        #pragma unroll
        for (int j = 0; j < 4; j++)
            #pragma unroll
            for (int q = 0; q < 4; q++) acc[i][j][q] = 0.f;

    const int KC = Kdim >> 6;

    auto issue = [&](int st) {
        const int k0 = st << 6;
        const uint32_t base = sb + (st % STAGES) * STG_T;
        #pragma unroll
        for (int p = 0; p < 4; p++)
            cp16(base + (ar0 + p * 32) * A_ROWB + ac16,
                 A8 + ((size_t)(bm + ar0 + p * 32) * Kdim + k0) * 2 + ac16);
        const uint32_t bb = base + A_STG;
        #pragma unroll
        for (int p = 0; p < 4; p++)
            cp16(bb + (br0 + p * 16) * B_ROWB + bc16,
                 W8 + ((size_t)(k0 + br0 + p * 16) * Wstr + bn) * 2 + bc16);
        asm volatile("cp.async.commit_group;" ::: "memory");
    };

    #pragma unroll
    for (int st = 0; st < STAGES - 1; st++) issue(st);

    for (int it = 0; it < KC; it++) {
        asm volatile("cp.async.wait_group %0;" :: "n"(STAGES - 2) : "memory");
        __syncthreads();
        if (it + STAGES - 1 < KC) issue(it + STAGES - 1);
        else asm volatile("cp.async.commit_group;" ::: "memory");

        const uint32_t Ab = sb + (it % STAGES) * STG_T;
        const uint32_t Bb = Ab + A_STG;
        #pragma unroll
        for (int ks = 0; ks < 4; ks++) {
            uint32_t af[4][4], bf[2][4];
            #pragma unroll
            for (int mf = 0; mf < 4; mf++)
                ldsm_x4(af[mf], Ab + (wm0 + mf * 16 + a_r) * A_ROWB + (ks * 16 + a_k) * 2);
            #pragma unroll
            for (int np = 0; np < 2; np++)
                ldsm_x4_t(bf[np], Bb + (ks * 16 + b_k) * B_ROWB + (wn0 + np * 16 + b_n) * 2);
            #pragma unroll
            for (int mf = 0; mf < 4; mf++) {
                #pragma unroll
                for (int nf = 0; nf < 4; nf++)
                    mma_bf16(acc[mf][nf], af[mf], bf[nf >> 1] + (nf & 1) * 2);
            }
        }
    }

    // ---- epilogue ----
    #pragma unroll
    for (int mf = 0; mf < 4; mf++) {
        const int row = bm + wm0 + mf * 16 + tq;
        #pragma unroll
        for (int nf = 0; nf < 4; nf++) {
            const int col = bn + wn0 + nf * 8 + 2 * tr;
            float v0 = acc[mf][nf][0];
            float v1 = acc[mf][nf][1];
            float v2 = acc[mf][nf][2];
            float v3 = acc[mf][nf][3];
            const size_t o0 = (size_t)row * Cstr + col;
            const size_t o1 = (size_t)(row + 8) * Cstr + col;
            if (MODE == 2) {
                const float2 r0 = *(const float2*)(sl.R + o0);
                const float2 r1 = *(const float2*)(sl.R + o1);
                const float2 g0 = bf2_to_f2(sl.G + o0);
                const float2 g1 = bf2_to_f2(sl.G + o1);
                v0 = fmaf(g0.x, v0, r0.x);
                v1 = fmaf(g0.y, v1, r0.y);
                v2 = fmaf(g1.x, v2, r1.x);
                v3 = fmaf(g1.y, v3, r1.y);
                *(float2*)(sl.C + o0) = make_float2(v0, v1);
                *(float2*)(sl.C + o1) = make_float2(v2, v3);
            } else {
                float b0 = 0.f, b1 = 0.f;
                if (sl.bias) { b0 = sl.bias[col]; b1 = sl.bias[col + 1]; }
                v0 += b0; v1 += b1; v2 += b0; v3 += b1;
                if (act == 1) {
                    v0 = 1.f / (1.f + __expf(-v0));
                    v1 = 1.f / (1.f + __expf(-v1));
                    v2 = 1.f / (1.f + __expf(-v2));
                    v3 = 1.f / (1.f + __expf(-v3));
                }
                if (MODE == 3) {
                    __nv_bfloat16* Cb = (__nv_bfloat16*)sl.C;
                    *(uint32_t*)(Cb + o0) = f2_to_bf16x2(v0, v1);
                    *(uint32_t*)(Cb + o1) = f2_to_bf16x2(v2, v3);
                } else {
                    *(float2*)(sl.C + o0) = make_float2(v0, v1);
                    *(float2*)(sl.C + o1) = make_float2(v2, v3);
                }
            }
        }
    }
}

// =================================================================================
// flash attention, tf32 mma, fused output gate: og = (softmax(..)@V) * gt, bf16 out.
// =================================================================================
#define QSTR 52
#define PSTR 68
#define FA_Q  0
#define FA_K  3328
#define FA_V  6656
#define FA_P  9984
#define FA_SMEM ((9984 + 64*PSTR)*4)   // 57344 bytes

__global__ __launch_bounds__(128) void flash_attn_kernel(
    const float* __restrict__ q, const float* __restrict__ k,
    const float* __restrict__ v, const float* __restrict__ z,
    const float* __restrict__ gt, __nv_bfloat16* __restrict__ og)
{
    extern __shared__ float fsm[];
    float* Qs = fsm + FA_Q;
    float* Ks = fsm + FA_K;
    float* Vs = fsm + FA_V;
    float* Ps = fsm + FA_P;

    const int tid = threadIdx.x, lane = tid & 31, wq = tid >> 5;
    const int tq = lane >> 2, tr = lane & 3;
    const int qt = blockIdx.x;
    const int hb = blockIdx.y;
    const int h = hb / B_, b = hb % B_;
    const int q0 = qt * 64;
    const float scale = 0.14433756729740643f;

    for (int e = tid; e < 64 * 12; e += 128) {
        const int r = e / 12, c4 = (e % 12) * 4;
        const float4 vq = *(const float4*)(q + ((size_t)(b * N_) + q0 + r) * D_ + h * HD_ + c4);
        uint4 u;
        u.x = f2tf32(vq.x); u.y = f2tf32(vq.y); u.z = f2tf32(vq.z); u.w = f2tf32(vq.w);
        *(uint4*)(Qs + r * QSTR + c4) = u;
    }
    __syncthreads();

    const int rowa = wq * 16 + tq;
    uint32_t qf[6][4];
    #pragma unroll
    for (int kk = 0; kk < 6; kk++) {
        qf[kk][0] = __float_as_uint(Qs[rowa * QSTR + kk * 8 + tr]);
        qf[kk][1] = __float_as_uint(Qs[(rowa + 8) * QSTR + kk * 8 + tr]);
        qf[kk][2] = __float_as_uint(Qs[rowa * QSTR + kk * 8 + tr + 4]);
        qf[kk][3] = __float_as_uint(Qs[(rowa + 8) * QSTR + kk * 8 + tr + 4]);
    }

    float m0 = -1e30f, m1 = -1e30f, l0 = 0.f, l1 = 0.f;
    float O[6][4];
    #pragma unroll
    for (int i = 0; i < 6; i++)
        #pragma unroll
        for (int j = 0; j < 4; j++) O[i][j] = 0.f;

    for (int t = 0; t < 16; t++) {
        __syncthreads();
        for (int e = tid; e < 64 * 12; e += 128) {
            const int r = e / 12, c4 = (e % 12) * 4;
            const size_t gof = ((size_t)(b * N_) + t * 64 + r) * D_ + h * HD_ + c4;
            const float4 vk = *(const float4*)(k + gof);
            const float4 vv = *(const float4*)(v + gof);
            uint4 uk, uv;
            uk.x = f2tf32(vk.x); uk.y = f2tf32(vk.y); uk.z = f2tf32(vk.z); uk.w = f2tf32(vk.w);
            uv.x = f2tf32(vv.x); uv.y = f2tf32(vv.y); uv.z = f2tf32(vv.z); uv.w = f2tf32(vv.w);
            *(uint4*)(Ks + r * QSTR + c4) = uk;
            *(uint4*)(Vs + r * QSTR + c4) = uv;
        }
        __syncthreads();

        float c[8][4];
        #pragma unroll
        for (int nf = 0; nf < 8; nf++)
            #pragma unroll
            for (int j = 0; j < 4; j++) c[nf][j] = 0.f;
        #pragma unroll
        for (int nf = 0; nf < 8; nf++) {
            #pragma unroll
            for (int kk = 0; kk < 6; kk++) {
                uint32_t bfv[2];
                bfv[0] = __float_as_uint(Ks[(nf * 8 + tq) * QSTR + kk * 8 + tr]);
                bfv[1] = __float_as_uint(Ks[(nf * 8 + tq) * QSTR + kk * 8 + tr + 4]);
                mma_m16n8k8(c[nf], qf[kk], bfv);
            }
        }

        float mx0 = -1e30f, mx1 = -1e30f;
        const size_t zb0 = (((size_t)hb) * N_ + q0 + rowa) * N_ + t * 64 + 2 * tr;
        #pragma unroll
        for (int nf = 0; nf < 8; nf++) {
            const float2 z0 = *(const float2*)(z + zb0 + nf * 8);
            const float2 z1 = *(const float2*)(z + zb0 + (size_t)8 * N_ + nf * 8);
            c[nf][0] = fmaf(c[nf][0], scale, z0.x);
            c[nf][1] = fmaf(c[nf][1], scale, z0.y);
            c[nf][2] = fmaf(c[nf][2], scale, z1.x);
            c[nf][3] = fmaf(c[nf][3], scale, z1.y);
            mx0 = fmaxf(mx0, fmaxf(c[nf][0], c[nf][1]));
            mx1 = fmaxf(mx1, fmaxf(c[nf][2], c[nf][3]));
        }
        mx0 = fmaxf(mx0, __shfl_xor_sync(0xffffffffu, mx0, 1));
        mx0 = fmaxf(mx0, __shfl_xor_sync(0xffffffffu, mx0, 2));
        mx1 = fmaxf(mx1, __shfl_xor_sync(0xffffffffu, mx1, 1));
        mx1 = fmaxf(mx1, __shfl_xor_sync(0xffffffffu, mx1, 2));
        const float mn0 = fmaxf(m0, mx0), mn1 = fmaxf(m1, mx1);
        const float a0 = __expf(m0 - mn0), a1 = __expf(m1 - mn1);

        float rs0 = 0.f, rs1 = 0.f;
        #pragma unroll
        for (int nf = 0; nf < 8; nf++) {
            const float p0 = __expf(c[nf][0] - mn0);
            const float p1 = __expf(c[nf][1] - mn0);
            const float p2 = __expf(c[nf][2] - mn1);
            const float p3 = __expf(c[nf][3] - mn1);
            rs0 += p0 + p1; rs1 += p2 + p3;
            uint2 u0, u1;
            u0.x = f2tf32(p0); u0.y = f2tf32(p1);
            u1.x = f2tf32(p2); u1.y = f2tf32(p3);
            *(uint2*)(Ps + rowa * PSTR + nf * 8 + 2 * tr)       = u0;
            *(uint2*)(Ps + (rowa + 8) * PSTR + nf * 8 + 2 * tr) = u1;
        }
        rs0 += __shfl_xor_sync(0xffffffffu, rs0, 1);
        rs0 += __shfl_xor_sync(0xffffffffu, rs0, 2);
        rs1 += __shfl_xor_sync(0xffffffffu, rs1, 1);
        rs1 += __shfl_xor_sync(0xffffffffu, rs1, 2);
        l0 = l0 * a0 + rs0;
        l1 = l1 * a1 + rs1;
        m0 = mn0; m1 = mn1;

        #pragma unroll
        for (int nf = 0; nf < 6; nf++) {
            O[nf][0] *= a0; O[nf][1] *= a0;
            O[nf][2] *= a1; O[nf][3] *= a1;
        }
        __syncwarp();

        #pragma unroll
        for (int ks = 0; ks < 8; ks++) {
            uint32_t pf[4];
            pf[0] = __float_as_uint(Ps[rowa * PSTR + ks * 8 + tr]);
            pf[1] = __float_as_uint(Ps[(rowa + 8) * PSTR + ks * 8 + tr]);
            pf[2] = __float_as_uint(Ps[rowa * PSTR + ks * 8 + tr + 4]);
            pf[3] = __float_as_uint(Ps[(rowa + 8) * PSTR + ks * 8 + tr + 4]);
            #pragma unroll
            for (int nf = 0; nf < 6; nf++) {
                uint32_t vf[2];
                vf[0] = __float_as_uint(Vs[(ks * 8 + tr) * QSTR + nf * 8 + tq]);
                vf[1] = __float_as_uint(Vs[(ks * 8 + tr + 4) * QSTR + nf * 8 + tq]);
                mma_m16n8k8(O[nf], pf, vf);
            }
        }
    }

    const float il0 = 1.f / l0, il1 = 1.f / l1;
    const size_t ob0 = ((size_t)(b * N_) + q0 + rowa) * D_ + h * HD_ + 2 * tr;
    #pragma unroll
    for (int nf = 0; nf < 6; nf++) {
        const float2 g0 = *(const float2*)(gt + ob0 + nf * 8);
        const float2 g1 = *(const float2*)(gt + ob0 + (size_t)8 * D_ + nf * 8);
        *(uint32_t*)(og + ob0 + nf * 8) =
            f2_to_bf16x2(O[nf][0] * il0 * g0.x, O[nf][1] * il0 * g0.y);
        *(uint32_t*)(og + ob0 + (size_t)8 * D_ + nf * 8) =
            f2_to_bf16x2(O[nf][2] * il1 * g1.x, O[nf][3] * il1 * g1.y);
    }
}

// ---------------- fused LN + adaLN combine: out_bf16 = ln(x)*c1 + c2 (c1,c2 bf16) --
__global__ __launch_bounds__(256) void ln_combine_kernel(const float* __restrict__ x,
                                                         const __nv_bfloat16* __restrict__ c1,
                                                         const __nv_bfloat16* __restrict__ c2,
                                                         __nv_bfloat16* __restrict__ out) {
    const int row = blockIdx.x;
    const float* xr = x + (size_t)row * D_;
    float lv[3];
    float s = 0.f;
    #pragma unroll
    for (int i = 0; i < 3; i++) { lv[i] = xr[threadIdx.x + i*256]; s += lv[i]; }
    float mean = block_reduce_sum(s) * (1.f / D_);
    float vs = 0.f;
    #pragma unroll
    for (int i = 0; i < 3; i++) { float d = lv[i] - mean; vs += d * d; }
    float var = block_reduce_sum(vs) * (1.f / D_);
    float rstd = rsqrtf(var + EPS_);
    const __nv_bfloat16* c1r = c1 + (size_t)row * D_;
    const __nv_bfloat16* c2r = c2 + (size_t)row * D_;
    __nv_bfloat16* orow = out + (size_t)row * D_;
    #pragma unroll
    for (int i = 0; i < 3; i++) {
        int c = threadIdx.x + i*256;
        float ln = (lv[i] - mean) * rstd;
        orow[c] = __float2bfloat16(fmaf(ln, __bfloat162float(c1r[c]), __bfloat162float(c2r[c])));
    }
}

// ---------------- swiglu ----------------
__global__ void ew_swiglu_kernel(const __nv_bfloat16* __restrict__ sw,
                                 const __nv_bfloat16* __restrict__ ab,
                                 uint2* __restrict__ out, int n4) {
    int i = blockIdx.x * blockDim.x + threadIdx.x;
    if (i < n4) {
        int e = i * 4;
        int row = e / HID_, j = e - row * HID_;
        const __nv_bfloat162* up = (const __nv_bfloat162*)(sw + (size_t)row * (2 * HID_) + j);
        const __nv_bfloat162* gp = (const __nv_bfloat162*)(sw + (size_t)row * (2 * HID_) + HID_ + j);
        const __nv_bfloat162* ap = (const __nv_bfloat162*)(ab + (size_t)i * 4);
        float2 u0 = __bfloat1622float2(up[0]), u1 = __bfloat1622float2(up[1]);
        float2 g0 = __bfloat1622float2(gp[0]), g1 = __bfloat1622float2(gp[1]);
        float2 a0 = __bfloat1622float2(ap[0]), a1 = __bfloat1622float2(ap[1]);
        float4 r;
        r.x = g0.x / (1.f + __expf(-g0.x)) * u0.x * a0.x;
        r.y = g0.y / (1.f + __expf(-g0.y)) * u0.y * a0.y;
        r.z = g1.x / (1.f + __expf(-g1.x)) * u1.x * a1.x;
        r.w = g1.y / (1.f + __expf(-g1.y)) * u1.y * a1.y;
        out[i] = f4_to_bf16x4(r);
    }
}

// ---------------- host orchestration ----------------
static void* symp(const void* s) { void* p = nullptr; cudaGetSymbolAddress(&p, s); return p; }

static GSlice mk(const __nv_bfloat16* A, const __nv_bfloat16* W, const float* bias,
                 const float* R, const __nv_bfloat16* G, void* C,
                 int K, int Wstride, int Cstride, int act) {
    GSlice g; g.A = A; g.W = W; g.bias = bias; g.R = R; g.G = G; g.C = (float*)C;
    g.K = K; g.Wstride = Wstride; g.Cstride = Cstride; g.act = act;
    return g;
}
template<int MODE, int STAGES = 3>
static void run_gemms(int Ndim, int nsl, GSlice a, GSlice b = GSlice(),
                      GSlice c = GSlice(), GSlice d = GSlice(),
                      GSlice e = GSlice(), GSlice f = GSlice()) {
    GPack pk; pk.s[0] = a; pk.s[1] = b; pk.s[2] = c; pk.s[3] = d; pk.s[4] = e; pk.s[5] = f;
    mma_gemm_kernel<MODE, STAGES><<<dim3(Ndim / 128, M_ / 128, nsl), 256, STAGES * STG_T>>>(pk, Ndim);
}

extern "C" void kernel_launch(void* const* d_in, const int* in_sizes, int n_in,
                              void* d_out, int out_size) {
    const float* a          = (const float*)d_in[0];
    const float* s          = (const float*)d_in[1];
    const float* z          = (const float*)d_in[2];
    const float* ad1_snw    = (const float*)d_in[3];
    const float* ad1_ssw    = (const float*)d_in[4];
    const float* ad1_ssb    = (const float*)d_in[5];
    const float* ad1_sbw    = (const float*)d_in[6];
    const float* q_w        = (const float*)d_in[7];
    const float* q_b        = (const float*)d_in[8];
    const float* k_w        = (const float*)d_in[9];
    const float* v_w        = (const float*)d_in[10];
    const float* g_w        = (const float*)d_in[11];
    const float* o_w        = (const float*)d_in[12];
    const float* outproj_w  = (const float*)d_in[13];
    const float* outproj_b  = (const float*)d_in[14];
    const float* ad2_snw    = (const float*)d_in[15];
    const float* ad2_ssw    = (const float*)d_in[16];
    const float* ad2_ssb    = (const float*)d_in[17];
    const float* ad2_sbw    = (const float*)d_in[18];
    const float* swish_w    = (const float*)d_in[19];
    const float* a2b_w      = (const float*)d_in[20];
    const float* b2a_w      = (const float*)d_in[21];
    const float* op_w       = (const float*)d_in[22];
    const float* op_b       = (const float*)d_in[23];
    float* out = (float*)d_out;

    cudaFuncSetAttribute((const void*)mma_gemm_kernel<0,3>, cudaFuncAttributeMaxDynamicSharedMemorySize, 3 * STG_T);
    cudaFuncSetAttribute((const void*)mma_gemm_kernel<3,3>, cudaFuncAttributeMaxDynamicSharedMemorySize, 3 * STG_T);
    cudaFuncSetAttribute((const void*)mma_gemm_kernel<2,6>, cudaFuncAttributeMaxDynamicSharedMemorySize, 6 * STG_T);
    cudaFuncSetAttribute((const void*)flash_attn_kernel, cudaFuncAttributeMaxDynamicSharedMemorySize, FA_SMEM);

    float *qb = (float*)symp(g_q), *kb = (float*)symp(g_k), *vb = (float*)symp(g_v);
    float *gt = (float*)symp(g_gt), *anew = (float*)symp(g_anew);
    __nv_bfloat16 *wb    = (__nv_bfloat16*)symp(g_wbf);
    __nv_bfloat16 *sbf   = (__nv_bfloat16*)symp(g_sbf);
    __nv_bfloat16 *sn1bf = (__nv_bfloat16*)symp(g_sn1bf);
    __nv_bfloat16 *sn2bf = (__nv_bfloat16*)symp(g_sn2bf);
    __nv_bfloat16 *c1bf  = (__nv_bfloat16*)symp(g_c1bf);
    __nv_bfloat16 *c2bf  = (__nv_bfloat16*)symp(g_c2bf);
    __nv_bfloat16 *c1bbf = (__nv_bfloat16*)symp(g_c1bbf);
    __nv_bfloat16 *c2bbf = (__nv_bfloat16*)symp(g_c2bbf);
    __nv_bfloat16 *sgbf  = (__nv_bfloat16*)symp(g_sgbf);
    __nv_bfloat16 *sg2bf = (__nv_bfloat16*)symp(g_sg2bf);
    __nv_bfloat16 *bmbf  = (__nv_bfloat16*)symp(g_bmbf);
    __nv_bfloat16 *ogbf  = (__nv_bfloat16*)symp(g_ogbf);
    __nv_bfloat16 *swbf  = (__nv_bfloat16*)symp(g_swbf);
    __nv_bfloat16 *abbf  = (__nv_bfloat16*)symp(g_abbf);
    __nv_bfloat16 *hidbf = (__nv_bfloat16*)symp(g_hidbf);

    const __nv_bfloat16 *w_ssw1 = wb,          *w_sbw1 = wb + DD_,
                        *w_outp = wb + 2*DD_,  *w_op   = wb + 3*DD_,
                        *w_q    = wb + 4*DD_,  *w_k    = wb + 5*DD_,
                        *w_v    = wb + 6*DD_,  *w_g    = wb + 7*DD_,
                        *w_o    = wb + 8*DD_,  *w_ssw2 = wb + 9*DD_,
                        *w_sbw2 = wb + 10*DD_, *w_swsh = wb + OFF_SWISH,
                        *w_a2b  = wb + OFF_A2B, *w_b2a = wb + OFF_B2A;

    const int n4MH = M_ * HID_ / 4;
    const int EW = 256;
    const int DD4 = DD_ / 4;

    // ===== combined: convert weights + s to bf16  ||  LN(s)*snw1, LN(s)*snw2 =====
    {
        CPack cp;
        const float* srcs[11] = {ad1_ssw, ad1_sbw, outproj_w, op_w, q_w, k_w,
                                 v_w, g_w, o_w, ad2_ssw, ad2_sbw};
        for (int i = 0; i < 11; i++) {
            cp.s[i].src = srcs[i]; cp.s[i].dst = wb + (size_t)i * DD_; cp.s[i].n4 = DD4;
        }
        cp.s[11].src = swish_w; cp.s[11].dst = wb + OFF_SWISH; cp.s[11].n4 = D_*2*HID_/4;
        cp.s[12].src = a2b_w;   cp.s[12].dst = wb + OFF_A2B;   cp.s[12].n4 = D_*HID_/4;
        cp.s[13].src = b2a_w;   cp.s[13].dst = wb + OFF_B2A;   cp.s[13].n4 = HID_*D_/4;
        cp.s[14].src = s;       cp.s[14].dst = sbf;            cp.s[14].n4 = M_*D_/4;
        conv_ln_kernel<<<dim3(M_, 17), 256>>>(cp, s, ad1_snw, ad2_snw, sn1bf, sn2bf);
    }

    // ===== pack1 (z=6): ALL s-dependent projections, bf16 outputs =====
    run_gemms<3>(D_, 6,
        mk(sn1bf, w_ssw1, ad1_ssb,   0, 0, c1bf,  D_, D_, D_, 1),
        mk(sn1bf, w_sbw1, 0,         0, 0, c2bf,  D_, D_, D_, 0),
        mk(sbf,   w_outp, outproj_b, 0, 0, sgbf,  D_, D_, D_, 1),
        mk(sbf,   w_op,   op_b,      0, 0, sg2bf, D_, D_, D_, 1),
        mk(sn2bf, w_ssw2, ad2_ssb,   0, 0, c1bbf, D_, D_, D_, 1),
        mk(sn2bf, w_sbw2, 0,         0, 0, c2bbf, D_, D_, D_, 0));

    // ===== fused LN(a) + adaLN1 combine -> bmbf =====
    ln_combine_kernel<<<M_, 256>>>(a, c1bf, c2bf, bmbf);

    // ===== pack2: QKVG =====
    run_gemms<0>(D_, 4,
        mk(bmbf, w_q, q_b, 0, 0, qb, D_, D_, D_, 0),
        mk(bmbf, w_k, 0,   0, 0, kb, D_, D_, D_, 0),
        mk(bmbf, w_v, 0,   0, 0, vb, D_, D_, D_, 0),
        mk(bmbf, w_g, 0,   0, 0, gt, D_, D_, D_, 1));

    // ===== flash attention with fused output gate (writes bf16 og) =====
    flash_attn_kernel<<<dim3(N_ / 64, H_ * B_), 128, FA_SMEM>>>(qb, kb, vb, z, gt, ogbf);

    // ===== o-proj: gated-residual epilogue (MODE=2, 6-stage deep pipeline) =====
    run_gemms<2, 6>(D_, 1,
        mk(ogbf, w_o, 0, a, sgbf, anew, D_, D_, D_, 2));   // anew = a + sg*(og@o_w)

    // ===== fused LN(anew) + adaLN2 combine -> bmbf =====
    ln_combine_kernel<<<M_, 256>>>(anew, c1bbf, c2bbf, bmbf);

    // ===== MLP: bf16 outputs (MODE=3) =====
    run_gemms<3>(HID_, 3,
        mk(bmbf, w_swsh,        0, 0, 0, swbf,        D_, 2*HID_, 2*HID_, 0),
        mk(bmbf, w_swsh + HID_, 0, 0, 0, swbf + HID_, D_, 2*HID_, 2*HID_, 0),
        mk(bmbf, w_a2b,         0, 0, 0, abbf,        D_, HID_,   HID_,   0));
    ew_swiglu_kernel<<<(n4MH + EW - 1) / EW, EW>>>(swbf, abbf, (uint2*)hidbf, n4MH);

    // ===== b2a: gated-residual epilogue (MODE=2, 6-stage deep pipeline) =====
    run_gemms<2, 6>(D_, 1,
        mk(hidbf, w_b2a, 0, anew, sg2bf, out, HID_, D_, D_, 2));  // out = anew + sg2*(hid@b2a)
}

// round 17
// speedup vs baseline: 1.0324x; 1.0324x over previous
#include <cuda_runtime.h>
#include <cuda_bf16.h>
#include <math.h>
#include <stdint.h>

#define B_   2
#define N_   1024
#define D_   768
#define H_   16
#define HD_  48
#define HID_ 1536
#define M_   (B_*N_)      // 2048
#define EPS_ 1e-5f

// ---------------- fp32 scratch ----------------
__device__ float g_anew[M_*D_];

// ---------------- bf16 scratch (16B aligned for cp.async) ----------------
#define DD_ 589824                            // 768*768
#define OFF_SWISH (11*DD_)
#define OFF_A2B   (OFF_SWISH + D_*2*HID_)
#define OFF_B2A   (OFF_A2B + D_*HID_)
#define WBF_TOTAL (OFF_B2A + HID_*D_)
__device__ __align__(16) __nv_bfloat16 g_wbf  [WBF_TOTAL];
__device__ __align__(16) __nv_bfloat16 g_sbf  [M_*D_];
__device__ __align__(16) __nv_bfloat16 g_sn1bf[M_*D_];
__device__ __align__(16) __nv_bfloat16 g_sn2bf[M_*D_];
__device__ __align__(16) __nv_bfloat16 g_c1bf [M_*D_];
__device__ __align__(16) __nv_bfloat16 g_c2bf [M_*D_];
__device__ __align__(16) __nv_bfloat16 g_c1bbf[M_*D_];
__device__ __align__(16) __nv_bfloat16 g_c2bbf[M_*D_];
__device__ __align__(16) __nv_bfloat16 g_sgbf [M_*D_];
__device__ __align__(16) __nv_bfloat16 g_sg2bf[M_*D_];
__device__ __align__(16) __nv_bfloat16 g_bmbf [M_*D_];
__device__ __align__(16) __nv_bfloat16 g_qbf  [M_*D_];
__device__ __align__(16) __nv_bfloat16 g_kbf  [M_*D_];
__device__ __align__(16) __nv_bfloat16 g_vbf  [M_*D_];
__device__ __align__(16) __nv_bfloat16 g_gtbf [M_*D_];
__device__ __align__(16) __nv_bfloat16 g_ogbf [M_*D_];
__device__ __align__(16) __nv_bfloat16 g_swbf [M_*2*HID_];
__device__ __align__(16) __nv_bfloat16 g_abbf [M_*HID_];
__device__ __align__(16) __nv_bfloat16 g_hidbf[M_*HID_];

// =================================================================================
// helpers
// =================================================================================
__device__ __forceinline__ uint32_t smem_u32(const void* p) {
    uint32_t a;
    asm("{ .reg .u64 t; cvta.to.shared.u64 t, %1; cvt.u32.u64 %0, t; }" : "=r"(a) : "l"(p));
    return a;
}
__device__ __forceinline__ uint32_t f2tf32(float f) {
    uint32_t u;
    asm("cvt.rna.tf32.f32 %0, %1;" : "=r"(u) : "f"(f));
    return u;
}
__device__ __forceinline__ void mma_m16n8k8(float* c, const uint32_t* a, const uint32_t* b) {
    asm volatile(
        "mma.sync.aligned.m16n8k8.row.col.f32.tf32.tf32.f32 "
        "{%0,%1,%2,%3}, {%4,%5,%6,%7}, {%8,%9}, {%0,%1,%2,%3};"
        : "+f"(c[0]), "+f"(c[1]), "+f"(c[2]), "+f"(c[3])
        : "r"(a[0]), "r"(a[1]), "r"(a[2]), "r"(a[3]), "r"(b[0]), "r"(b[1]));
}
__device__ __forceinline__ void mma_bf16(float* c, const uint32_t* a, const uint32_t* b) {
    asm volatile(
        "mma.sync.aligned.m16n8k16.row.col.f32.bf16.bf16.f32 "
        "{%0,%1,%2,%3}, {%4,%5,%6,%7}, {%8,%9}, {%0,%1,%2,%3};"
        : "+f"(c[0]), "+f"(c[1]), "+f"(c[2]), "+f"(c[3])
        : "r"(a[0]), "r"(a[1]), "r"(a[2]), "r"(a[3]), "r"(b[0]), "r"(b[1]));
}
__device__ __forceinline__ void ldsm_x4(uint32_t* r, uint32_t addr) {
    asm volatile("ldmatrix.sync.aligned.m8n8.x4.shared.b16 {%0,%1,%2,%3}, [%4];"
        : "=r"(r[0]), "=r"(r[1]), "=r"(r[2]), "=r"(r[3]) : "r"(addr));
}
__device__ __forceinline__ void ldsm_x4_t(uint32_t* r, uint32_t addr) {
    asm volatile("ldmatrix.sync.aligned.m8n8.x4.trans.shared.b16 {%0,%1,%2,%3}, [%4];"
        : "=r"(r[0]), "=r"(r[1]), "=r"(r[2]), "=r"(r[3]) : "r"(addr));
}
__device__ __forceinline__ uint2 f4_to_bf16x4(float4 v) {
    __nv_bfloat162 lo = __float22bfloat162_rn(make_float2(v.x, v.y));
    __nv_bfloat162 hi = __float22bfloat162_rn(make_float2(v.z, v.w));
    uint2 r;
    r.x = *(uint32_t*)&lo;
    r.y = *(uint32_t*)&hi;
    return r;
}
__device__ __forceinline__ uint32_t f2_to_bf16x2(float a, float b) {
    __nv_bfloat162 p = __float22bfloat162_rn(make_float2(a, b));
    return *(uint32_t*)&p;
}
__device__ __forceinline__ float2 bf2_to_f2(const __nv_bfloat16* p) {
    return __bfloat1622float2(*(const __nv_bfloat162*)p);
}
__device__ __forceinline__ void cp16(uint32_t saddr, const void* gaddr) {
    asm volatile("cp.async.cg.shared.global [%0], [%1], 16;" :: "r"(saddr), "l"(gaddr));
}

// ---------------- block reduction ----------------
__device__ __forceinline__ float block_reduce_sum(float v) {
    __shared__ float sh[8];
    __shared__ float res;
    __syncthreads();
    #pragma unroll
    for (int o = 16; o > 0; o >>= 1) v += __shfl_down_sync(0xffffffffu, v, o);
    int lane = threadIdx.x & 31, w = threadIdx.x >> 5;
    if (lane == 0) sh[w] = v;
    __syncthreads();
    if (w == 0) {
        v = (lane < 8) ? sh[lane] : 0.f;
        #pragma unroll
        for (int o = 4; o > 0; o >>= 1) v += __shfl_down_sync(0xffffffffu, v, o);
        if (lane == 0) res = v;
    }
    __syncthreads();
    return res;
}

// =================================================================================
// combined kernel: y<15 -> fp32->bf16 conversion segments (grid-stride);
//                  y==15 -> bf16 ln(s)*w1; y==16 -> bf16 ln(s)*w2
// =================================================================================
struct CSeg { const float* src; __nv_bfloat16* dst; int n4; };
struct CPack { CSeg s[15]; };
__global__ __launch_bounds__(256) void conv_ln_kernel(CPack pk,
                                                      const float* __restrict__ x,
                                                      const float* __restrict__ w1,
                                                      const float* __restrict__ w2,
                                                      __nv_bfloat16* __restrict__ o1,
                                                      __nv_bfloat16* __restrict__ o2) {
    if (blockIdx.y < 15) {
        const CSeg sg = pk.s[blockIdx.y];
        for (int i = blockIdx.x * 256 + threadIdx.x; i < sg.n4; i += gridDim.x * 256) {
            ((uint2*)sg.dst)[i] = f4_to_bf16x4(((const float4*)sg.src)[i]);
        }
    } else {
        const int row = blockIdx.x;
        const float* xr = x + (size_t)row * D_;
        float lv[3];
        float s = 0.f;
        #pragma unroll
        for (int i = 0; i < 3; i++) { lv[i] = xr[threadIdx.x + i*256]; s += lv[i]; }
        float mean = block_reduce_sum(s) * (1.f / D_);
        float vs = 0.f;
        #pragma unroll
        for (int i = 0; i < 3; i++) { float d = lv[i] - mean; vs += d * d; }
        float var = block_reduce_sum(vs) * (1.f / D_);
        float rstd = rsqrtf(var + EPS_);
        const float* w = (blockIdx.y == 15) ? w1 : w2;
        __nv_bfloat16* orow = ((blockIdx.y == 15) ? o1 : o2) + (size_t)row * D_;
        #pragma unroll
        for (int i = 0; i < 3; i++) {
            int c = threadIdx.x + i*256;
            orow[c] = __float2bfloat16((lv[i] - mean) * rstd * w[c]);
        }
    }
}

// =================================================================================
// multi-slice bf16 GEMM: 128x128x64 iteration, cp.async 3-stage pipeline.
//   MODE=0: fp32 C = acc+bias (act=1 -> sigmoid)
//   MODE=2: fp32 C = R + G*acc   (R fp32, G bf16)
//   MODE=3: bf16 C = acc+bias (act=1 -> sigmoid)
// =================================================================================
struct GSlice {
    const __nv_bfloat16* A; const __nv_bfloat16* W; const float* bias;
    const float* R; const __nv_bfloat16* G; float* C;
    int K; int Wstride; int Cstride; int act;
};
struct GPack { GSlice s[6]; };

#define A_ROWB 144
#define B_ROWB 272
#define A_STG  (128*A_ROWB)         // 18432 B
#define STG_T  (A_STG + 64*B_ROWB)  // 35840 B per stage
#define GEMM_SMEM (3*STG_T)         // 107520 B

template<int MODE>
__global__ __launch_bounds__(256, 2) void mma_gemm_kernel(GPack pk, int Ndim)
{
    extern __shared__ char sm[];
    const uint32_t sb = smem_u32(sm);

    const GSlice sl = pk.s[blockIdx.z];
    const char* A8 = (const char*)sl.A;
    const char* W8 = (const char*)sl.W;
    const int Kdim = sl.K, Wstr = sl.Wstride, Cstr = sl.Cstride, act = sl.act;

    const int tid  = threadIdx.x;
    const int lane = tid & 31, wid = tid >> 5;
    const int wm0  = (wid >> 2) * 64;
    const int wn0  = (wid & 3) * 32;
    const int tq   = lane >> 2, tr = lane & 3;
    const int bm   = blockIdx.y * 128, bn = blockIdx.x * 128;

    const int ar0 = tid >> 3,  ac16 = (tid & 7) * 16;
    const int br0 = tid >> 4,  bc16 = (tid & 15) * 16;

    const int lm  = lane >> 3;
    const int li  = lane & 7;
    const int a_r = (lm & 1) * 8 + li, a_k = (lm >> 1) * 8;
    const int b_k = (lm & 1) * 8 + li, b_n = (lm >> 1) * 8;

    float acc[4][4][4];
    #pragma unroll
    for (int i = 0; i < 4; i++)
        #pragma unroll
        for (int j = 0; j < 4; j++)
            #pragma unroll
            for (int q = 0; q < 4; q++) acc[i][j][q] = 0.f;

    const int KC = Kdim >> 6;

    auto issue = [&](int st) {
        const int k0 = st << 6;
        const uint32_t base = sb + (st % 3) * STG_T;
        #pragma unroll
        for (int p = 0; p < 4; p++)
            cp16(base + (ar0 + p * 32) * A_ROWB + ac16,
                 A8 + ((size_t)(bm + ar0 + p * 32) * Kdim + k0) * 2 + ac16);
        const uint32_t bb = base + A_STG;
        #pragma unroll
        for (int p = 0; p < 4; p++)
            cp16(bb + (br0 + p * 16) * B_ROWB + bc16,
                 W8 + ((size_t)(k0 + br0 + p * 16) * Wstr + bn) * 2 + bc16);
        asm volatile("cp.async.commit_group;" ::: "memory");
    };

    issue(0); issue(1);

    for (int it = 0; it < KC; it++) {
        asm volatile("cp.async.wait_group 1;" ::: "memory");
        __syncthreads();
        if (it + 2 < KC) issue(it + 2);
        else asm volatile("cp.async.commit_group;" ::: "memory");

        const uint32_t Ab = sb + (it % 3) * STG_T;
        const uint32_t Bb = Ab + A_STG;
        #pragma unroll
        for (int ks = 0; ks < 4; ks++) {
            uint32_t af[4][4], bf[2][4];
            #pragma unroll
            for (int mf = 0; mf < 4; mf++)
                ldsm_x4(af[mf], Ab + (wm0 + mf * 16 + a_r) * A_ROWB + (ks * 16 + a_k) * 2);
            #pragma unroll
            for (int np = 0; np < 2; np++)
                ldsm_x4_t(bf[np], Bb + (ks * 16 + b_k) * B_ROWB + (wn0 + np * 16 + b_n) * 2);
            #pragma unroll
            for (int mf = 0; mf < 4; mf++) {
                #pragma unroll
                for (int nf = 0; nf < 4; nf++)
                    mma_bf16(acc[mf][nf], af[mf], bf[nf >> 1] + (nf & 1) * 2);
            }
        }
    }

    // ---- epilogue ----
    #pragma unroll
    for (int mf = 0; mf < 4; mf++) {
        const int row = bm + wm0 + mf * 16 + tq;
        #pragma unroll
        for (int nf = 0; nf < 4; nf++) {
            const int col = bn + wn0 + nf * 8 + 2 * tr;
            float v0 = acc[mf][nf][0];
            float v1 = acc[mf][nf][1];
            float v2 = acc[mf][nf][2];
            float v3 = acc[mf][nf][3];
            const size_t o0 = (size_t)row * Cstr + col;
            const size_t o1 = (size_t)(row + 8) * Cstr + col;
            if (MODE == 2) {
                const float2 r0 = *(const float2*)(sl.R + o0);
                const float2 r1 = *(const float2*)(sl.R + o1);
                const float2 g0 = bf2_to_f2(sl.G + o0);
                const float2 g1 = bf2_to_f2(sl.G + o1);
                v0 = fmaf(g0.x, v0, r0.x);
                v1 = fmaf(g0.y, v1, r0.y);
                v2 = fmaf(g1.x, v2, r1.x);
                v3 = fmaf(g1.y, v3, r1.y);
                *(float2*)(sl.C + o0) = make_float2(v0, v1);
                *(float2*)(sl.C + o1) = make_float2(v2, v3);
            } else {
                float b0 = 0.f, b1 = 0.f;
                if (sl.bias) { b0 = sl.bias[col]; b1 = sl.bias[col + 1]; }
                v0 += b0; v1 += b1; v2 += b0; v3 += b1;
                if (act == 1) {
                    v0 = 1.f / (1.f + __expf(-v0));
                    v1 = 1.f / (1.f + __expf(-v1));
                    v2 = 1.f / (1.f + __expf(-v2));
                    v3 = 1.f / (1.f + __expf(-v3));
                }
                if (MODE == 3) {
                    __nv_bfloat16* Cb = (__nv_bfloat16*)sl.C;
                    *(uint32_t*)(Cb + o0) = f2_to_bf16x2(v0, v1);
                    *(uint32_t*)(Cb + o1) = f2_to_bf16x2(v2, v3);
                } else {
                    *(float2*)(sl.C + o0) = make_float2(v0, v1);
                    *(float2*)(sl.C + o1) = make_float2(v2, v3);
                }
            }
        }
    }
}

// =================================================================================
// flash attention, tf32 mma, bf16 global q/k/v/gt (converted to tf32 at load).
// Fused output gate: og = (softmax(..)@V) * gt, bf16 out.
// =================================================================================
#define QSTR 52
#define PSTR 68
#define FA_Q  0
#define FA_K  3328
#define FA_V  6656
#define FA_P  9984
#define FA_SMEM ((9984 + 64*PSTR)*4)   // 57344 bytes

__global__ __launch_bounds__(128) void flash_attn_kernel(
    const __nv_bfloat16* __restrict__ q, const __nv_bfloat16* __restrict__ k,
    const __nv_bfloat16* __restrict__ v, const float* __restrict__ z,
    const __nv_bfloat16* __restrict__ gt, __nv_bfloat16* __restrict__ og)
{
    extern __shared__ float fsm[];
    float* Qs = fsm + FA_Q;
    float* Ks = fsm + FA_K;
    float* Vs = fsm + FA_V;
    float* Ps = fsm + FA_P;

    const int tid = threadIdx.x, lane = tid & 31, wq = tid >> 5;
    const int tq = lane >> 2, tr = lane & 3;
    const int qt = blockIdx.x;
    const int hb = blockIdx.y;
    const int h = hb / B_, b = hb % B_;
    const int q0 = qt * 64;
    const float scale = 0.14433756729740643f;

    // load Q tile (64 x 48 bf16 -> tf32 smem); 6 chunks of 8 per row
    for (int e = tid; e < 64 * 6; e += 128) {
        const int r = e / 6, c8 = (e % 6) * 8;
        const uint4 raw = *(const uint4*)(q + ((size_t)(b * N_) + q0 + r) * D_ + h * HD_ + c8);
        const uint32_t* rw = (const uint32_t*)&raw;
        float* dst = Qs + r * QSTR + c8;
        #pragma unroll
        for (int j = 0; j < 4; j++) {
            const float2 f = __bfloat1622float2(*(const __nv_bfloat162*)&rw[j]);
            ((uint32_t*)dst)[2*j]   = f2tf32(f.x);
            ((uint32_t*)dst)[2*j+1] = f2tf32(f.y);
        }
    }
    __syncthreads();

    const int rowa = wq * 16 + tq;
    uint32_t qf[6][4];
    #pragma unroll
    for (int kk = 0; kk < 6; kk++) {
        qf[kk][0] = __float_as_uint(Qs[rowa * QSTR + kk * 8 + tr]);
        qf[kk][1] = __float_as_uint(Qs[(rowa + 8) * QSTR + kk * 8 + tr]);
        qf[kk][2] = __float_as_uint(Qs[rowa * QSTR + kk * 8 + tr + 4]);
        qf[kk][3] = __float_as_uint(Qs[(rowa + 8) * QSTR + kk * 8 + tr + 4]);
    }

    float m0 = -1e30f, m1 = -1e30f, l0 = 0.f, l1 = 0.f;
    float O[6][4];
    #pragma unroll
    for (int i = 0; i < 6; i++)
        #pragma unroll
        for (int j = 0; j < 4; j++) O[i][j] = 0.f;

    for (int t = 0; t < 16; t++) {
        __syncthreads();
        for (int e = tid; e < 64 * 6; e += 128) {
            const int r = e / 6, c8 = (e % 6) * 8;
            const size_t gof = ((size_t)(b * N_) + t * 64 + r) * D_ + h * HD_ + c8;
            const uint4 rk = *(const uint4*)(k + gof);
            const uint4 rv = *(const uint4*)(v + gof);
            const uint32_t* pk = (const uint32_t*)&rk;
            const uint32_t* pv = (const uint32_t*)&rv;
            float* dk = Ks + r * QSTR + c8;
            float* dv = Vs + r * QSTR + c8;
            #pragma unroll
            for (int j = 0; j < 4; j++) {
                const float2 fk = __bfloat1622float2(*(const __nv_bfloat162*)&pk[j]);
                const float2 fv = __bfloat1622float2(*(const __nv_bfloat162*)&pv[j]);
                ((uint32_t*)dk)[2*j]   = f2tf32(fk.x);
                ((uint32_t*)dk)[2*j+1] = f2tf32(fk.y);
                ((uint32_t*)dv)[2*j]   = f2tf32(fv.x);
                ((uint32_t*)dv)[2*j+1] = f2tf32(fv.y);
            }
        }
        __syncthreads();

        float c[8][4];
        #pragma unroll
        for (int nf = 0; nf < 8; nf++)
            #pragma unroll
            for (int j = 0; j < 4; j++) c[nf][j] = 0.f;
        #pragma unroll
        for (int nf = 0; nf < 8; nf++) {
            #pragma unroll
            for (int kk = 0; kk < 6; kk++) {
                uint32_t bfv[2];
                bfv[0] = __float_as_uint(Ks[(nf * 8 + tq) * QSTR + kk * 8 + tr]);
                bfv[1] = __float_as_uint(Ks[(nf * 8 + tq) * QSTR + kk * 8 + tr + 4]);
                mma_m16n8k8(c[nf], qf[kk], bfv);
            }
        }

        float mx0 = -1e30f, mx1 = -1e30f;
        const size_t zb0 = (((size_t)hb) * N_ + q0 + rowa) * N_ + t * 64 + 2 * tr;
        #pragma unroll
        for (int nf = 0; nf < 8; nf++) {
            const float2 z0 = *(const float2*)(z + zb0 + nf * 8);
            const float2 z1 = *(const float2*)(z + zb0 + (size_t)8 * N_ + nf * 8);
            c[nf][0] = fmaf(c[nf][0], scale, z0.x);
            c[nf][1] = fmaf(c[nf][1], scale, z0.y);
            c[nf][2] = fmaf(c[nf][2], scale, z1.x);
            c[nf][3] = fmaf(c[nf][3], scale, z1.y);
            mx0 = fmaxf(mx0, fmaxf(c[nf][0], c[nf][1]));
            mx1 = fmaxf(mx1, fmaxf(c[nf][2], c[nf][3]));
        }
        mx0 = fmaxf(mx0, __shfl_xor_sync(0xffffffffu, mx0, 1));
        mx0 = fmaxf(mx0, __shfl_xor_sync(0xffffffffu, mx0, 2));
        mx1 = fmaxf(mx1, __shfl_xor_sync(0xffffffffu, mx1, 1));
        mx1 = fmaxf(mx1, __shfl_xor_sync(0xffffffffu, mx1, 2));
        const float mn0 = fmaxf(m0, mx0), mn1 = fmaxf(m1, mx1);
        const float a0 = __expf(m0 - mn0), a1 = __expf(m1 - mn1);

        float rs0 = 0.f, rs1 = 0.f;
        #pragma unroll
        for (int nf = 0; nf < 8; nf++) {
            const float p0 = __expf(c[nf][0] - mn0);
            const float p1 = __expf(c[nf][1] - mn0);
            const float p2 = __expf(c[nf][2] - mn1);
            const float p3 = __expf(c[nf][3] - mn1);
            rs0 += p0 + p1; rs1 += p2 + p3;
            uint2 u0, u1;
            u0.x = f2tf32(p0); u0.y = f2tf32(p1);
            u1.x = f2tf32(p2); u1.y = f2tf32(p3);
            *(uint2*)(Ps + rowa * PSTR + nf * 8 + 2 * tr)       = u0;
            *(uint2*)(Ps + (rowa + 8) * PSTR + nf * 8 + 2 * tr) = u1;
        }
        rs0 += __shfl_xor_sync(0xffffffffu, rs0, 1);
        rs0 += __shfl_xor_sync(0xffffffffu, rs0, 2);
        rs1 += __shfl_xor_sync(0xffffffffu, rs1, 1);
        rs1 += __shfl_xor_sync(0xffffffffu, rs1, 2);
        l0 = l0 * a0 + rs0;
        l1 = l1 * a1 + rs1;
        m0 = mn0; m1 = mn1;

        #pragma unroll
        for (int nf = 0; nf < 6; nf++) {
            O[nf][0] *= a0; O[nf][1] *= a0;
            O[nf][2] *= a1; O[nf][3] *= a1;
        }
        __syncwarp();

        #pragma unroll
        for (int ks = 0; ks < 8; ks++) {
            uint32_t pf[4];
            pf[0] = __float_as_uint(Ps[rowa * PSTR + ks * 8 + tr]);
            pf[1] = __float_as_uint(Ps[(rowa + 8) * PSTR + ks * 8 + tr]);
            pf[2] = __float_as_uint(Ps[rowa * PSTR + ks * 8 + tr + 4]);
            pf[3] = __float_as_uint(Ps[(rowa + 8) * PSTR + ks * 8 + tr + 4]);
            #pragma unroll
            for (int nf = 0; nf < 6; nf++) {
                uint32_t vf[2];
                vf[0] = __float_as_uint(Vs[(ks * 8 + tr) * QSTR + nf * 8 + tq]);
                vf[1] = __float_as_uint(Vs[(ks * 8 + tr + 4) * QSTR + nf * 8 + tq]);
                mma_m16n8k8(O[nf], pf, vf);
            }
        }
    }

    const float il0 = 1.f / l0, il1 = 1.f / l1;
    const size_t ob0 = ((size_t)(b * N_) + q0 + rowa) * D_ + h * HD_ + 2 * tr;
    #pragma unroll
    for (int nf = 0; nf < 6; nf++) {
        const float2 g0 = bf2_to_f2(gt + ob0 + nf * 8);
        const float2 g1 = bf2_to_f2(gt + ob0 + (size_t)8 * D_ + nf * 8);
        *(uint32_t*)(og + ob0 + nf * 8) =
            f2_to_bf16x2(O[nf][0] * il0 * g0.x, O[nf][1] * il0 * g0.y);
        *(uint32_t*)(og + ob0 + (size_t)8 * D_ + nf * 8) =
            f2_to_bf16x2(O[nf][2] * il1 * g1.x, O[nf][3] * il1 * g1.y);
    }
}

// ---------------- fused LN + adaLN combine: out_bf16 = ln(x)*c1 + c2 (c1,c2 bf16) --
__global__ __launch_bounds__(256) void ln_combine_kernel(const float* __restrict__ x,
                                                         const __nv_bfloat16* __restrict__ c1,
                                                         const __nv_bfloat16* __restrict__ c2,
                                                         __nv_bfloat16* __restrict__ out) {
    const int row = blockIdx.x;
    const float* xr = x + (size_t)row * D_;
    float lv[3];
    float s = 0.f;
    #pragma unroll
    for (int i = 0; i < 3; i++) { lv[i] = xr[threadIdx.x + i*256]; s += lv[i]; }
    float mean = block_reduce_sum(s) * (1.f / D_);
    float vs = 0.f;
    #pragma unroll
    for (int i = 0; i < 3; i++) { float d = lv[i] - mean; vs += d * d; }
    float var = block_reduce_sum(vs) * (1.f / D_);
    float rstd = rsqrtf(var + EPS_);
    const __nv_bfloat16* c1r = c1 + (size_t)row * D_;
    const __nv_bfloat16* c2r = c2 + (size_t)row * D_;
    __nv_bfloat16* orow = out + (size_t)row * D_;
    #pragma unroll
    for (int i = 0; i < 3; i++) {
        int c = threadIdx.x + i*256;
        float ln = (lv[i] - mean) * rstd;
        orow[c] = __float2bfloat16(fmaf(ln, __bfloat162float(c1r[c]), __bfloat162float(c2r[c])));
    }
}

// ---------------- swiglu ----------------
__global__ void ew_swiglu_kernel(const __nv_bfloat16* __restrict__ sw,
                                 const __nv_bfloat16* __restrict__ ab,
                                 uint2* __restrict__ out, int n4) {
    int i = blockIdx.x * blockDim.x + threadIdx.x;
    if (i < n4) {
        int e = i * 4;
        int row = e / HID_, j = e - row * HID_;
        const __nv_bfloat162* up = (const __nv_bfloat162*)(sw + (size_t)row * (2 * HID_) + j);
        const __nv_bfloat162* gp = (const __nv_bfloat162*)(sw + (size_t)row * (2 * HID_) + HID_ + j);
        const __nv_bfloat162* ap = (const __nv_bfloat162*)(ab + (size_t)i * 4);
        float2 u0 = __bfloat1622float2(up[0]), u1 = __bfloat1622float2(up[1]);
        float2 g0 = __bfloat1622float2(gp[0]), g1 = __bfloat1622float2(gp[1]);
        float2 a0 = __bfloat1622float2(ap[0]), a1 = __bfloat1622float2(ap[1]);
        float4 r;
        r.x = g0.x / (1.f + __expf(-g0.x)) * u0.x * a0.x;
        r.y = g0.y / (1.f + __expf(-g0.y)) * u0.y * a0.y;
        r.z = g1.x / (1.f + __expf(-g1.x)) * u1.x * a1.x;
        r.w = g1.y / (1.f + __expf(-g1.y)) * u1.y * a1.y;
        out[i] = f4_to_bf16x4(r);
    }
}

// ---------------- host orchestration ----------------
static void* symp(const void* s) { void* p = nullptr; cudaGetSymbolAddress(&p, s); return p; }

static GSlice mk(const __nv_bfloat16* A, const __nv_bfloat16* W, const float* bias,
                 const float* R, const __nv_bfloat16* G, void* C,
                 int K, int Wstride, int Cstride, int act) {
    GSlice g; g.A = A; g.W = W; g.bias = bias; g.R = R; g.G = G; g.C = (float*)C;
    g.K = K; g.Wstride = Wstride; g.Cstride = Cstride; g.act = act;
    return g;
}
template<int MODE>
static void run_gemms(int Ndim, int nsl, GSlice a, GSlice b = GSlice(),
                      GSlice c = GSlice(), GSlice d = GSlice(),
                      GSlice e = GSlice(), GSlice f = GSlice()) {
    GPack pk; pk.s[0] = a; pk.s[1] = b; pk.s[2] = c; pk.s[3] = d; pk.s[4] = e; pk.s[5] = f;
    mma_gemm_kernel<MODE><<<dim3(Ndim / 128, M_ / 128, nsl), 256, GEMM_SMEM>>>(pk, Ndim);
}

extern "C" void kernel_launch(void* const* d_in, const int* in_sizes, int n_in,
                              void* d_out, int out_size) {
    const float* a          = (const float*)d_in[0];
    const float* s          = (const float*)d_in[1];
    const float* z          = (const float*)d_in[2];
    const float* ad1_snw    = (const float*)d_in[3];
    const float* ad1_ssw    = (const float*)d_in[4];
    const float* ad1_ssb    = (const float*)d_in[5];
    const float* ad1_sbw    = (const float*)d_in[6];
    const float* q_w        = (const float*)d_in[7];
    const float* q_b        = (const float*)d_in[8];
    const float* k_w        = (const float*)d_in[9];
    const float* v_w        = (const float*)d_in[10];
    const float* g_w        = (const float*)d_in[11];
    const float* o_w        = (const float*)d_in[12];
    const float* outproj_w  = (const float*)d_in[13];
    const float* outproj_b  = (const float*)d_in[14];
    const float* ad2_snw    = (const float*)d_in[15];
    const float* ad2_ssw    = (const float*)d_in[16];
    const float* ad2_ssb    = (const float*)d_in[17];
    const float* ad2_sbw    = (const float*)d_in[18];
    const float* swish_w    = (const float*)d_in[19];
    const float* a2b_w      = (const float*)d_in[20];
    const float* b2a_w      = (const float*)d_in[21];
    const float* op_w       = (const float*)d_in[22];
    const float* op_b       = (const float*)d_in[23];
    float* out = (float*)d_out;

    cudaFuncSetAttribute((const void*)mma_gemm_kernel<0>, cudaFuncAttributeMaxDynamicSharedMemorySize, GEMM_SMEM);
    cudaFuncSetAttribute((const void*)mma_gemm_kernel<2>, cudaFuncAttributeMaxDynamicSharedMemorySize, GEMM_SMEM);
    cudaFuncSetAttribute((const void*)mma_gemm_kernel<3>, cudaFuncAttributeMaxDynamicSharedMemorySize, GEMM_SMEM);
    cudaFuncSetAttribute((const void*)flash_attn_kernel, cudaFuncAttributeMaxDynamicSharedMemorySize, FA_SMEM);

    float *anew = (float*)symp(g_anew);
    __nv_bfloat16 *wb    = (__nv_bfloat16*)symp(g_wbf);
    __nv_bfloat16 *sbf   = (__nv_bfloat16*)symp(g_sbf);
    __nv_bfloat16 *sn1bf = (__nv_bfloat16*)symp(g_sn1bf);
    __nv_bfloat16 *sn2bf = (__nv_bfloat16*)symp(g_sn2bf);
    __nv_bfloat16 *c1bf  = (__nv_bfloat16*)symp(g_c1bf);
    __nv_bfloat16 *c2bf  = (__nv_bfloat16*)symp(g_c2bf);
    __nv_bfloat16 *c1bbf = (__nv_bfloat16*)symp(g_c1bbf);
    __nv_bfloat16 *c2bbf = (__nv_bfloat16*)symp(g_c2bbf);
    __nv_bfloat16 *sgbf  = (__nv_bfloat16*)symp(g_sgbf);
    __nv_bfloat16 *sg2bf = (__nv_bfloat16*)symp(g_sg2bf);
    __nv_bfloat16 *bmbf  = (__nv_bfloat16*)symp(g_bmbf);
    __nv_bfloat16 *qbf   = (__nv_bfloat16*)symp(g_qbf);
    __nv_bfloat16 *kbf   = (__nv_bfloat16*)symp(g_kbf);
    __nv_bfloat16 *vbf   = (__nv_bfloat16*)symp(g_vbf);
    __nv_bfloat16 *gtbf  = (__nv_bfloat16*)symp(g_gtbf);
    __nv_bfloat16 *ogbf  = (__nv_bfloat16*)symp(g_ogbf);
    __nv_bfloat16 *swbf  = (__nv_bfloat16*)symp(g_swbf);
    __nv_bfloat16 *abbf  = (__nv_bfloat16*)symp(g_abbf);
    __nv_bfloat16 *hidbf = (__nv_bfloat16*)symp(g_hidbf);

    const __nv_bfloat16 *w_ssw1 = wb,          *w_sbw1 = wb + DD_,
                        *w_outp = wb + 2*DD_,  *w_op   = wb + 3*DD_,
                        *w_q    = wb + 4*DD_,  *w_k    = wb + 5*DD_,
                        *w_v    = wb + 6*DD_,  *w_g    = wb + 7*DD_,
                        *w_o    = wb + 8*DD_,  *w_ssw2 = wb + 9*DD_,
                        *w_sbw2 = wb + 10*DD_, *w_swsh = wb + OFF_SWISH,
                        *w_a2b  = wb + OFF_A2B, *w_b2a = wb + OFF_B2A;

    const int n4MH = M_ * HID_ / 4;
    const int EW = 256;
    const int DD4 = DD_ / 4;

    // ===== combined: convert weights + s to bf16  ||  LN(s)*snw1, LN(s)*snw2 =====
    {
        CPack cp;
        const float* srcs[11] = {ad1_ssw, ad1_sbw, outproj_w, op_w, q_w, k_w,
                                 v_w, g_w, o_w, ad2_ssw, ad2_sbw};
        for (int i = 0; i < 11; i++) {
            cp.s[i].src = srcs[i]; cp.s[i].dst = wb + (size_t)i * DD_; cp.s[i].n4 = DD4;
        }
        cp.s[11].src = swish_w; cp.s[11].dst = wb + OFF_SWISH; cp.s[11].n4 = D_*2*HID_/4;
        cp.s[12].src = a2b_w;   cp.s[12].dst = wb + OFF_A2B;   cp.s[12].n4 = D_*HID_/4;
        cp.s[13].src = b2a_w;   cp.s[13].dst = wb + OFF_B2A;   cp.s[13].n4 = HID_*D_/4;
        cp.s[14].src = s;       cp.s[14].dst = sbf;            cp.s[14].n4 = M_*D_/4;
        conv_ln_kernel<<<dim3(M_, 17), 256>>>(cp, s, ad1_snw, ad2_snw, sn1bf, sn2bf);
    }

    // ===== pack1 (z=6): ALL s-dependent projections, bf16 outputs =====
    run_gemms<3>(D_, 6,
        mk(sn1bf, w_ssw1, ad1_ssb,   0, 0, c1bf,  D_, D_, D_, 1),
        mk(sn1bf, w_sbw1, 0,         0, 0, c2bf,  D_, D_, D_, 0),
        mk(sbf,   w_outp, outproj_b, 0, 0, sgbf,  D_, D_, D_, 1),
        mk(sbf,   w_op,   op_b,      0, 0, sg2bf, D_, D_, D_, 1),
        mk(sn2bf, w_ssw2, ad2_ssb,   0, 0, c1bbf, D_, D_, D_, 1),
        mk(sn2bf, w_sbw2, 0,         0, 0, c2bbf, D_, D_, D_, 0));

    // ===== fused LN(a) + adaLN1 combine -> bmbf =====
    ln_combine_kernel<<<M_, 256>>>(a, c1bf, c2bf, bmbf);

    // ===== pack2: QKVG, bf16 outputs =====
    run_gemms<3>(D_, 4,
        mk(bmbf, w_q, q_b, 0, 0, qbf,  D_, D_, D_, 0),
        mk(bmbf, w_k, 0,   0, 0, kbf,  D_, D_, D_, 0),
        mk(bmbf, w_v, 0,   0, 0, vbf,  D_, D_, D_, 0),
        mk(bmbf, w_g, 0,   0, 0, gtbf, D_, D_, D_, 1));

    // ===== flash attention (bf16 inputs) with fused output gate (bf16 og) =====
    flash_attn_kernel<<<dim3(N_ / 64, H_ * B_), 128, FA_SMEM>>>(qbf, kbf, vbf, z, gtbf, ogbf);

    // ===== o-proj: gated-residual epilogue (MODE=2) =====
    run_gemms<2>(D_, 1,
        mk(ogbf, w_o, 0, a, sgbf, anew, D_, D_, D_, 2));   // anew = a + sg*(og@o_w)

    // ===== fused LN(anew) + adaLN2 combine -> bmbf =====
    ln_combine_kernel<<<M_, 256>>>(anew, c1bbf, c2bbf, bmbf);

    // ===== MLP: bf16 outputs (MODE=3) =====
    run_gemms<3>(HID_, 3,
        mk(bmbf, w_swsh,        0, 0, 0, swbf,        D_, 2*HID_, 2*HID_, 0),
        mk(bmbf, w_swsh + HID_, 0, 0, 0, swbf + HID_, D_, 2*HID_, 2*HID_, 0),
        mk(bmbf, w_a2b,         0, 0, 0, abbf,        D_, HID_,   HID_,   0));
    ew_swiglu_kernel<<<(n4MH + EW - 1) / EW, EW>>>(swbf, abbf, (uint2*)hidbf, n4MH);

    // ===== b2a: gated-residual epilogue (MODE=2) =====
    run_gemms<2>(D_, 1,
        mk(hidbf, w_b2a, 0, anew, sg2bf, out, HID_, D_, D_, 2));  // out = anew + sg2*(hid@b2a)
}